// round 12
// baseline (speedup 1.0000x reference)
#include <cuda_runtime.h>
#include <cuda_bf16.h>
#include <cuda_pipeline.h>
#include <mma.h>
#include <math.h>
#include <stdint.h>

using namespace nvcuda;

// Problem constants (DebugGCN: N=100000 nodes, E=640000 edges, 128->128->40)
#define NMAX 100000
#define EMAX 640000
#define FIN 128
#define FH  128
#define FC  40
#define FCP 48

// ---- gemm1: 64 rows/block, A hi/lo + B hi/lo, ld=136 (272B stride, LDSM conflict-free)
#define G1_ROWS 64
#define LDA 136
#define OFF_AH 0
#define OFF_AL 17408          // 64*136*2
#define OFF_BH 34816
#define OFF_BL 69632
#define SM1_TOTAL 104448      // 2 CTAs/SM
#define W1_IMG_F4 2176        // 128*136*2/16

// ---- gemm2 (fused agg1): 64 rows/block, A ld=136, B ld=72 (144B stride, conflict-free)
#define LDB2 72
#define OFF2_AH 0
#define OFF2_AL 17408
#define OFF2_BH 34816
#define OFF2_BL 53248         // + 128*72*2
#define SM2_TOTAL 71680       // 3 CTAs/SM
#define W2_IMG_F4 1152        // 128*72*2/16

// -------- scratch (device globals) --------
__device__ float4 g_y4[(size_t)(NMAX + 128) * (FH / 4)];   // dinv*(x@W1)
__device__ float4 g_z4[(size_t)(NMAX + 128) * (FCP / 4)];  // h'@W2 (padded 48)
__device__ float  g_dinv[NMAX];
__device__ int    g_deg[NMAX];
__device__ int    g_cursor[NMAX];
__device__ int    g_rowstart[NMAX];
__device__ int    g_adj[EMAX];
__device__ int    g_bsums[512];
__device__ int    g_is64;
__device__ float4 g_W1h4[W1_IMG_F4];
__device__ float4 g_W1l4[W1_IMG_F4];
__device__ float4 g_W2h4[W2_IMG_F4];
__device__ float4 g_W2l4[W2_IMG_F4];

__device__ __forceinline__ uint32_t pack_bf16x2(float a, float b) {
    __nv_bfloat16 ha = __float2bfloat16_rn(a);
    __nv_bfloat16 hb = __float2bfloat16_rn(b);
    return ((uint32_t)__bfloat16_as_ushort(hb) << 16) | __bfloat16_as_ushort(ha);
}
// split 8 floats (2 float4) into hi uint4 + lo uint4
__device__ __forceinline__ void split8(float4 v0, float4 v1, uint4* hi, uint4* lo) {
    float f[8] = {v0.x, v0.y, v0.z, v0.w, v1.x, v1.y, v1.z, v1.w};
    uint32_t hw[4], lw[4];
    #pragma unroll
    for (int p = 0; p < 4; p++) {
        float a = f[2 * p], b = f[2 * p + 1];
        __nv_bfloat16 ha = __float2bfloat16_rn(a);
        __nv_bfloat16 hb = __float2bfloat16_rn(b);
        hw[p] = ((uint32_t)__bfloat16_as_ushort(hb) << 16) | __bfloat16_as_ushort(ha);
        lw[p] = pack_bf16x2(a - __bfloat162float(ha), b - __bfloat162float(hb));
    }
    *hi = *(uint4*)hw; *lo = *(uint4*)lw;
}

// ---------------- merged zero + edge-dtype detect ----------------
__global__ void zdetect_kernel(const int* __restrict__ ei32, int words, int n) {
    int i = blockIdx.x * blockDim.x + threadIdx.x;
    if (i < n) { g_deg[i] = 0; g_cursor[i] = 0; }
    if (blockIdx.x == 0) {
        __shared__ int flag;
        if (threadIdx.x == 0) flag = 0;
        __syncthreads();
        int acc = 0;
        for (int j = threadIdx.x * 2 + 1; j < words; j += 2 * 256 * 16) acc |= ei32[j];
        if (acc) atomicOr(&flag, 1);
        __syncthreads();
        if (threadIdx.x == 0) g_is64 = (flag == 0) ? 1 : 0;
    }
}

__device__ __forceinline__ int load_node(const void* ei, size_t idx) {
    if (g_is64) return (int)((const long long*)ei)[idx];
    return ((const int*)ei)[idx];
}

__global__ void hist_kernel(const void* __restrict__ ei, int E) {
    int e = blockIdx.x * blockDim.x + threadIdx.x;
    if (e < E) atomicAdd(&g_deg[load_node(ei, (size_t)E + e)], 1);
}

// ---------------- dinv + W1/W2 hi-lo split prep ----------------
__global__ void dinv_prep_kernel(const float* __restrict__ W1,
                                 const float* __restrict__ W2, int n) {
    int i = blockIdx.x * blockDim.x + threadIdx.x;
    if (i < n) g_dinv[i] = rsqrtf((float)(g_deg[i] + 1));
    if (i < FIN * FH) {
        int k = i >> 7, c = i & 127;
        float w = W1[i];
        __nv_bfloat16 h = __float2bfloat16_rn(w);
        __nv_bfloat16 l = __float2bfloat16_rn(w - __bfloat162float(h));
        ((__nv_bfloat16*)g_W1h4)[k * LDA + c] = h;
        ((__nv_bfloat16*)g_W1l4)[k * LDA + c] = l;
    }
    if (i < FIN * 8) {
        int k = i >> 3, c = 128 + (i & 7);
        ((__nv_bfloat16*)g_W1h4)[k * LDA + c] = __float2bfloat16_rn(0.f);
        ((__nv_bfloat16*)g_W1l4)[k * LDA + c] = __float2bfloat16_rn(0.f);
    }
    if (i < FH * LDB2) {
        int k = i / LDB2, c = i % LDB2;
        float w = (c < FC) ? W2[k * FC + c] : 0.f;
        __nv_bfloat16 h = __float2bfloat16_rn(w);
        __nv_bfloat16 l = __float2bfloat16_rn(w - __bfloat162float(h));
        ((__nv_bfloat16*)g_W2h4)[k * LDB2 + c] = h;
        ((__nv_bfloat16*)g_W2l4)[k * LDB2 + c] = l;
    }
}

// ---------------- GEMM1: y = (dinv.x) @ W1  (64-row blocks, 2 CTA/SM) ----------------
__global__ void __launch_bounds__(256) gemm1_wmma_kernel(const float* __restrict__ x, int n) {
    extern __shared__ char smem[];
    int tid = threadIdx.x;
    int r0 = blockIdx.x * G1_ROWS;

    // async-copy W1 hi/lo images (68KB) into smem
    {
        float4* dbh = (float4*)(smem + OFF_BH);
        float4* dbl = (float4*)(smem + OFF_BL);
        for (int i = tid; i < W1_IMG_F4; i += 256) {
            __pipeline_memcpy_async(dbh + i, g_W1h4 + i, 16);
            __pipeline_memcpy_async(dbl + i, g_W1l4 + i, 16);
        }
        __pipeline_commit();
    }

    // stage A: 64 rows, 4 threads/row (32 feats each); scale by dinv, split hi/lo
    {
        int r = tid >> 2, q = tid & 3;
        int gr = r0 + r; if (gr >= n) gr = n - 1;
        float di = g_dinv[gr];
        const float4* xr = (const float4*)(x + (size_t)gr * FIN) + q * 8;
        char* rowh = smem + OFF_AH + r * (LDA * 2) + q * 64;
        char* rowl = smem + OFF_AL + r * (LDA * 2) + q * 64;
        #pragma unroll
        for (int j = 0; j < 4; j++) {
            float4 v0 = xr[j * 2], v1 = xr[j * 2 + 1];
            v0.x *= di; v0.y *= di; v0.z *= di; v0.w *= di;
            v1.x *= di; v1.y *= di; v1.z *= di; v1.w *= di;
            uint4 hi, lo;
            split8(v0, v1, &hi, &lo);
            *(uint4*)(rowh + j * 16) = hi;
            *(uint4*)(rowl + j * 16) = lo;
        }
    }
    __pipeline_wait_prior(0);
    __syncthreads();

    int wid = tid >> 5;
    int wm = wid >> 1;            // 0..3 (16-row m-tile)
    int nh = wid & 1;             // 0..1 (64-col half)

    wmma::fragment<wmma::accumulator, 16, 16, 16, float> fc[4];
    #pragma unroll
    for (int nt = 0; nt < 4; nt++) wmma::fill_fragment(fc[nt], 0.f);

    const __nv_bfloat16* Ah = (const __nv_bfloat16*)(smem + OFF_AH) + wm * 16 * LDA;
    const __nv_bfloat16* Al = (const __nv_bfloat16*)(smem + OFF_AL) + wm * 16 * LDA;
    const __nv_bfloat16* Bh = (const __nv_bfloat16*)(smem + OFF_BH) + nh * 64;
    const __nv_bfloat16* Bl = (const __nv_bfloat16*)(smem + OFF_BL) + nh * 64;

    #pragma unroll
    for (int ks = 0; ks < 8; ks++) {
        wmma::fragment<wmma::matrix_a, 16, 16, 16, __nv_bfloat16, wmma::row_major> fah, fal;
        wmma::load_matrix_sync(fah, Ah + ks * 16, LDA);
        wmma::load_matrix_sync(fal, Al + ks * 16, LDA);
        #pragma unroll
        for (int nt = 0; nt < 4; nt++) {
            wmma::fragment<wmma::matrix_b, 16, 16, 16, __nv_bfloat16, wmma::row_major> fbh, fbl;
            wmma::load_matrix_sync(fbh, Bh + ks * 16 * LDA + nt * 16, LDA);
            wmma::load_matrix_sync(fbl, Bl + ks * 16 * LDA + nt * 16, LDA);
            wmma::mma_sync(fc[nt], fah, fbh, fc[nt]);
            wmma::mma_sync(fc[nt], fal, fbh, fc[nt]);
            wmma::mma_sync(fc[nt], fah, fbl, fc[nt]);
        }
    }

    float* yout = (float*)g_y4;
    #pragma unroll
    for (int nt = 0; nt < 4; nt++)
        wmma::store_matrix_sync(yout + (size_t)(r0 + wm * 16) * FH + nh * 64 + nt * 16,
                                fc[nt], FH, wmma::mem_row_major);
}

// ---------------- scans / scatter ----------------
__global__ void scan_block_kernel(int n) {
    __shared__ int s[512];
    int t = threadIdx.x;
    int i = blockIdx.x * 512 + t;
    int v = (i < n) ? g_deg[i] : 0;
    s[t] = v;
    __syncthreads();
    #pragma unroll
    for (int off = 1; off < 512; off <<= 1) {
        int u = (t >= off) ? s[t - off] : 0;
        __syncthreads();
        s[t] += u;
        __syncthreads();
    }
    if (i < n) g_rowstart[i] = s[t] - v;
    if (t == 511) g_bsums[blockIdx.x] = s[511];
}

__global__ void scan_top_kernel(int nb) {
    __shared__ int s[256];
    int t = threadIdx.x;
    int v = (t < nb) ? g_bsums[t] : 0;
    s[t] = v;
    __syncthreads();
    #pragma unroll
    for (int off = 1; off < 256; off <<= 1) {
        int u = (t >= off) ? s[t - off] : 0;
        __syncthreads();
        s[t] += u;
        __syncthreads();
    }
    if (t < nb) g_bsums[t] = s[t] - v;
}

__global__ void scan_add_kernel(int n) {
    int i = blockIdx.x * 512 + threadIdx.x;
    if (i < n) g_rowstart[i] += g_bsums[blockIdx.x];
}

__global__ void scatter_kernel(const void* __restrict__ ei, int E) {
    int e = blockIdx.x * blockDim.x + threadIdx.x;
    if (e < E) {
        int d = load_node(ei, (size_t)E + e);
        int s = load_node(ei, (size_t)e);
        int p = atomicAdd(&g_cursor[d], 1);
        g_adj[g_rowstart[d] + p] = s;
    }
}

// ---------------- GEMM2 (fused agg1): z = relu_agg(y) @ W2 ----------------
// 64 rows/block, 256 thr, 3 CTA/SM. Staging does the layer-1 aggregation inline:
// h'[r] = relu(dinv*(sum_{nbr} y + y_self) + b1) * dinv  -> bf16 hi/lo in smem.
__global__ void __launch_bounds__(256) gemm2_wmma_kernel(const float* __restrict__ b1, int n) {
    extern __shared__ char smem[];
    int tid = threadIdx.x;
    int r0 = blockIdx.x * 64;

    {
        float4* dbh = (float4*)(smem + OFF2_BH);
        float4* dbl = (float4*)(smem + OFF2_BL);
        for (int i = tid; i < W2_IMG_F4; i += 256) {
            __pipeline_memcpy_async(dbh + i, g_W2h4 + i, 16);
            __pipeline_memcpy_async(dbl + i, g_W2l4 + i, 16);
        }
        __pipeline_commit();
    }

    // fused aggregation staging: 4 threads/row, 32 feats each
    {
        int r = tid >> 2, q = tid & 3;
        int gr = r0 + r; if (gr >= n) gr = n - 1;
        float di = g_dinv[gr];
        int s0 = g_rowstart[gr];
        int d  = g_deg[gr];
        const float4* yb = g_y4 + q * 8;
        float4 acc[8];
        #pragma unroll
        for (int j = 0; j < 8; j++) acc[j] = yb[(size_t)gr * 32 + j];   // self
        for (int e = 0; e < d; e++) {
            int s = g_adj[s0 + e];
            #pragma unroll
            for (int j = 0; j < 8; j++) {
                float4 v = yb[(size_t)s * 32 + j];
                acc[j].x += v.x; acc[j].y += v.y; acc[j].z += v.z; acc[j].w += v.w;
            }
        }
        const float4* bb = (const float4*)b1 + q * 8;
        char* rowh = smem + OFF2_AH + r * (LDA * 2) + q * 64;
        char* rowl = smem + OFF2_AL + r * (LDA * 2) + q * 64;
        #pragma unroll
        for (int j = 0; j < 4; j++) {
            float4 a0 = acc[j * 2], a1 = acc[j * 2 + 1];
            float4 c0 = bb[j * 2],  c1 = bb[j * 2 + 1];
            float4 o0, o1;
            o0.x = fmaxf(fmaf(a0.x, di, c0.x), 0.f) * di;
            o0.y = fmaxf(fmaf(a0.y, di, c0.y), 0.f) * di;
            o0.z = fmaxf(fmaf(a0.z, di, c0.z), 0.f) * di;
            o0.w = fmaxf(fmaf(a0.w, di, c0.w), 0.f) * di;
            o1.x = fmaxf(fmaf(a1.x, di, c1.x), 0.f) * di;
            o1.y = fmaxf(fmaf(a1.y, di, c1.y), 0.f) * di;
            o1.z = fmaxf(fmaf(a1.z, di, c1.z), 0.f) * di;
            o1.w = fmaxf(fmaf(a1.w, di, c1.w), 0.f) * di;
            uint4 hi, lo;
            split8(o0, o1, &hi, &lo);
            *(uint4*)(rowh + j * 16) = hi;
            *(uint4*)(rowl + j * 16) = lo;
        }
    }
    __pipeline_wait_prior(0);
    __syncthreads();

    int wid = tid >> 5;
    const __nv_bfloat16* Ah = (const __nv_bfloat16*)(smem + OFF2_AH);
    const __nv_bfloat16* Al = (const __nv_bfloat16*)(smem + OFF2_AL);
    const __nv_bfloat16* Bh = (const __nv_bfloat16*)(smem + OFF2_BH);
    const __nv_bfloat16* Bl = (const __nv_bfloat16*)(smem + OFF2_BL);
    float* zout = (float*)g_z4;

    // 12 warp-jobs (4 m-tiles x 3 n-tiles) over 8 warps
    for (int job = wid; job < 12; job += 8) {
        int mt = job / 3, nt = job % 3;
        wmma::fragment<wmma::accumulator, 16, 16, 16, float> fc;
        wmma::fill_fragment(fc, 0.f);
        #pragma unroll
        for (int ks = 0; ks < 8; ks++) {
            wmma::fragment<wmma::matrix_a, 16, 16, 16, __nv_bfloat16, wmma::row_major> fah, fal;
            wmma::fragment<wmma::matrix_b, 16, 16, 16, __nv_bfloat16, wmma::row_major> fbh, fbl;
            wmma::load_matrix_sync(fah, Ah + mt * 16 * LDA + ks * 16, LDA);
            wmma::load_matrix_sync(fal, Al + mt * 16 * LDA + ks * 16, LDA);
            wmma::load_matrix_sync(fbh, Bh + ks * 16 * LDB2 + nt * 16, LDB2);
            wmma::load_matrix_sync(fbl, Bl + ks * 16 * LDB2 + nt * 16, LDB2);
            wmma::mma_sync(fc, fah, fbh, fc);
            wmma::mma_sync(fc, fal, fbh, fc);
            wmma::mma_sync(fc, fah, fbl, fc);
        }
        wmma::store_matrix_sync(zout + (size_t)(r0 + mt * 16) * FCP + nt * 16, fc, FCP,
                                wmma::mem_row_major);
    }
}

// ---------------- agg2 + log_softmax (2 nodes per warp, z stride 48) ----------------
__global__ __launch_bounds__(256) void agg2_kernel(const float* __restrict__ b2,
                                                   float* __restrict__ out, int n) {
    int warp = (blockIdx.x * blockDim.x + threadIdx.x) >> 5;
    int lane = threadIdx.x & 31;
    int half = lane >> 4;
    int hl = lane & 15;
    int node = warp * 2 + half;
    bool valid = (node < n);
    bool act = valid && (hl < 10);
    float4 acc = make_float4(0.f, 0.f, 0.f, 0.f);
    if (act) acc = g_z4[(size_t)node * 12 + hl];
    int s0 = valid ? g_rowstart[node] : 0;
    int d  = valid ? g_deg[node] : 0;
    for (int j = 0; j < d; j++) {
        int s = g_adj[s0 + j];
        if (act) {
            float4 v = g_z4[(size_t)s * 12 + hl];
            acc.x += v.x; acc.y += v.y; acc.z += v.z; acc.w += v.w;
        }
    }
    float di = valid ? g_dinv[node] : 0.f;
    float4 l = make_float4(-INFINITY, -INFINITY, -INFINITY, -INFINITY);
    if (act) {
        float4 bb = *(const float4*)&b2[hl * 4];
        l.x = fmaf(acc.x, di, bb.x);
        l.y = fmaf(acc.y, di, bb.y);
        l.z = fmaf(acc.z, di, bb.z);
        l.w = fmaf(acc.w, di, bb.w);
    }
    float m = fmaxf(fmaxf(l.x, l.y), fmaxf(l.z, l.w));
    #pragma unroll
    for (int off = 8; off >= 1; off >>= 1)
        m = fmaxf(m, __shfl_xor_sync(0xffffffffu, m, off));
    float ssum = 0.f;
    if (act)
        ssum = expf(l.x - m) + expf(l.y - m) + expf(l.z - m) + expf(l.w - m);
    #pragma unroll
    for (int off = 8; off >= 1; off >>= 1)
        ssum += __shfl_xor_sync(0xffffffffu, ssum, off);
    float lse = m + logf(ssum);
    if (act) {
        float4 o;
        o.x = l.x - lse; o.y = l.y - lse; o.z = l.z - lse; o.w = l.w - lse;
        *(float4*)&out[(size_t)node * FC + hl * 4] = o;
    }
}

// ---------------- launch ----------------
extern "C" void kernel_launch(void* const* d_in, const int* in_sizes, int n_in,
                              void* d_out, int out_size) {
    const float* x  = (const float*)d_in[0];
    const void*  ei = d_in[1];
    const float* W1 = (const float*)d_in[2];
    const float* b1 = (const float*)d_in[3];
    const float* W2 = (const float*)d_in[4];
    const float* b2 = (const float*)d_in[5];
    float* out = (float*)d_out;

    int n = in_sizes[0] / FIN;   // 100000
    int E = in_sizes[1] / 2;     // 640000
    int NB = (n + 511) / 512;

    static cudaStream_t s2 = nullptr;
    static cudaEvent_t eFork = nullptr, eJoin = nullptr;
    static int init_done = 0;
    if (!init_done) {
        cudaFuncSetAttribute(gemm1_wmma_kernel,
                             cudaFuncAttributeMaxDynamicSharedMemorySize, SM1_TOTAL);
        cudaFuncSetAttribute(gemm2_wmma_kernel,
                             cudaFuncAttributeMaxDynamicSharedMemorySize, SM2_TOTAL);
        cudaStreamCreateWithFlags(&s2, cudaStreamNonBlocking);
        cudaEventCreateWithFlags(&eFork, cudaEventDisableTiming);
        cudaEventCreateWithFlags(&eJoin, cudaEventDisableTiming);
        init_done = 1;
    }

    // serial prologue
    zdetect_kernel<<<(n + 255) / 256, 256>>>((const int*)ei, 2 * E, n);
    hist_kernel<<<(E + 255) / 256, 256>>>(ei, E);

    // fork: CSR chain on s2 runs concurrently with dinv_prep + gemm1
    cudaEventRecord(eFork, 0);
    cudaStreamWaitEvent(s2, eFork, 0);

    scan_block_kernel<<<NB, 512, 0, s2>>>(n);
    scan_top_kernel<<<1, 256, 0, s2>>>(NB);
    scan_add_kernel<<<NB, 512, 0, s2>>>(n);
    scatter_kernel<<<(E + 255) / 256, 256, 0, s2>>>(ei, E);
    cudaEventRecord(eJoin, s2);

    dinv_prep_kernel<<<(n + 255) / 256, 256>>>(W1, W2, n);
    gemm1_wmma_kernel<<<(n + G1_ROWS - 1) / G1_ROWS, 256, SM1_TOTAL>>>(x, n);

    // join before fused gemm2 (needs CSR + y)
    cudaStreamWaitEvent(0, eJoin, 0);

    gemm2_wmma_kernel<<<(n + 63) / 64, 256, SM2_TOTAL>>>(b1, n);
    int warps2 = (n + 1) / 2;
    agg2_kernel<<<(warps2 * 32 + 255) / 256, 256>>>(b2, out, n);
}

// round 13
// speedup vs baseline: 1.2815x; 1.2815x over previous
#include <cuda_runtime.h>
#include <cuda_bf16.h>
#include <cuda_pipeline.h>
#include <mma.h>
#include <math.h>
#include <stdint.h>

using namespace nvcuda;

// Problem constants (DebugGCN: N=100000 nodes, E=640000 edges, 128->128->40)
#define NMAX 100000
#define EMAX 640000
#define FIN 128
#define FH  128
#define FC  40
#define FCP 48

#define LDA 136               // bf16 ld: 272B stride -> LDSM conflict-free
#define W1_IMG_F4 2176        // 128*136*2/16

// ---- gemm1 persistent: B hi/lo + A-conv hi/lo (64 rows) + 2 raw x buffers
#define OFF1_BH   0
#define OFF1_BL   34816
#define OFF1_AH   69632
#define OFF1_AL   87040
#define OFF1_RAW0 104448
#define OFF1_RAW1 137216
#define SM1_TOTAL 169984      // 166KB, 1 CTA/SM persistent

// ---- gemm2: 128 rows/block, A ld=136, B ld=72 (144B stride, conflict-free)
#define LDB2 72
#define OFF2_AH 0
#define OFF2_AL 34816
#define OFF2_BH 69632
#define OFF2_BL 88064
#define SM2_TOTAL 106496
#define W2_IMG_F4 1152

// -------- scratch (device globals) --------
__device__ float4 g_y4[(size_t)(NMAX + 128) * (FH / 4)];   // dinv*(x@W1)
__device__ uint4  g_hh[(size_t)(NMAX + 128) * 16];         // h' hi bf16 rows
__device__ uint4  g_hl[(size_t)(NMAX + 128) * 16];         // h' lo
__device__ float4 g_z4[(size_t)(NMAX + 128) * (FCP / 4)];  // h'@W2 (padded 48)
__device__ float  g_dinv[NMAX];
__device__ int    g_deg[NMAX];
__device__ int    g_cursor[NMAX];
__device__ int    g_rowstart[NMAX];
__device__ int    g_adj[EMAX];
__device__ int    g_bsums[512];
__device__ int    g_is64;
__device__ float4 g_W1h4[W1_IMG_F4];
__device__ float4 g_W1l4[W1_IMG_F4];
__device__ float4 g_W2h4[W2_IMG_F4];
__device__ float4 g_W2l4[W2_IMG_F4];

__device__ __forceinline__ uint32_t pack_bf16x2(float a, float b) {
    __nv_bfloat16 ha = __float2bfloat16_rn(a);
    __nv_bfloat16 hb = __float2bfloat16_rn(b);
    return ((uint32_t)__bfloat16_as_ushort(hb) << 16) | __bfloat16_as_ushort(ha);
}
__device__ __forceinline__ void split8(float4 v0, float4 v1, uint4* hi, uint4* lo) {
    float f[8] = {v0.x, v0.y, v0.z, v0.w, v1.x, v1.y, v1.z, v1.w};
    uint32_t hw[4], lw[4];
    #pragma unroll
    for (int p = 0; p < 4; p++) {
        float a = f[2 * p], b = f[2 * p + 1];
        __nv_bfloat16 ha = __float2bfloat16_rn(a);
        __nv_bfloat16 hb = __float2bfloat16_rn(b);
        hw[p] = ((uint32_t)__bfloat16_as_ushort(hb) << 16) | __bfloat16_as_ushort(ha);
        lw[p] = pack_bf16x2(a - __bfloat162float(ha), b - __bfloat162float(hb));
    }
    *hi = *(uint4*)hw; *lo = *(uint4*)lw;
}

// ---------------- merged zero + edge-dtype detect ----------------
__global__ void zdetect_kernel(const int* __restrict__ ei32, int words, int n) {
    int i = blockIdx.x * blockDim.x + threadIdx.x;
    if (i < n) { g_deg[i] = 0; g_cursor[i] = 0; }
    if (blockIdx.x == 0) {
        __shared__ int flag;
        if (threadIdx.x == 0) flag = 0;
        __syncthreads();
        int acc = 0;
        for (int j = threadIdx.x * 2 + 1; j < words; j += 2 * 256 * 16) acc |= ei32[j];
        if (acc) atomicOr(&flag, 1);
        __syncthreads();
        if (threadIdx.x == 0) g_is64 = (flag == 0) ? 1 : 0;
    }
}

__device__ __forceinline__ int load_node(const void* ei, size_t idx) {
    if (g_is64) return (int)((const long long*)ei)[idx];
    return ((const int*)ei)[idx];
}

__global__ void hist_kernel(const void* __restrict__ ei, int E) {
    int e = blockIdx.x * blockDim.x + threadIdx.x;
    if (e < E) atomicAdd(&g_deg[load_node(ei, (size_t)E + e)], 1);
}

// ---------------- dinv + W1/W2 hi-lo split prep ----------------
__global__ void dinv_prep_kernel(const float* __restrict__ W1,
                                 const float* __restrict__ W2, int n) {
    int i = blockIdx.x * blockDim.x + threadIdx.x;
    if (i < n) g_dinv[i] = rsqrtf((float)(g_deg[i] + 1));
    if (i < FIN * FH) {
        int k = i >> 7, c = i & 127;
        float w = W1[i];
        __nv_bfloat16 h = __float2bfloat16_rn(w);
        __nv_bfloat16 l = __float2bfloat16_rn(w - __bfloat162float(h));
        ((__nv_bfloat16*)g_W1h4)[k * LDA + c] = h;
        ((__nv_bfloat16*)g_W1l4)[k * LDA + c] = l;
    }
    if (i < FIN * 8) {
        int k = i >> 3, c = 128 + (i & 7);
        ((__nv_bfloat16*)g_W1h4)[k * LDA + c] = __float2bfloat16_rn(0.f);
        ((__nv_bfloat16*)g_W1l4)[k * LDA + c] = __float2bfloat16_rn(0.f);
    }
    if (i < FH * LDB2) {
        int k = i / LDB2, c = i % LDB2;
        float w = (c < FC) ? W2[k * FC + c] : 0.f;
        __nv_bfloat16 h = __float2bfloat16_rn(w);
        __nv_bfloat16 l = __float2bfloat16_rn(w - __bfloat162float(h));
        ((__nv_bfloat16*)g_W2h4)[k * LDB2 + c] = h;
        ((__nv_bfloat16*)g_W2l4)[k * LDB2 + c] = l;
    }
}

// ---------------- GEMM1: persistent, B loaded once, double-buffered raw-x ----------------
__global__ void __launch_bounds__(256) gemm1_wmma_kernel(const float* __restrict__ x,
                                                         int n, int ntiles) {
    extern __shared__ char smem[];
    int tid = threadIdx.x;

    // group 0: B images + raw tile(blockIdx.x)
    {
        float4* dbh = (float4*)(smem + OFF1_BH);
        float4* dbl = (float4*)(smem + OFF1_BL);
        for (int i = tid; i < W1_IMG_F4; i += 256) {
            __pipeline_memcpy_async(dbh + i, g_W1h4 + i, 16);
            __pipeline_memcpy_async(dbl + i, g_W1l4 + i, 16);
        }
    }
    // issue raw-x copy for tile into buffer b
    #define ISSUE_RAW(tile, b) do {                                          \
        float4* dst = (float4*)(smem + ((b) ? OFF1_RAW1 : OFF1_RAW0));       \
        int base = (tile) * 64;                                              \
        for (int i = tid; i < 2048; i += 256) {                              \
            int rr = i >> 5, cc = i & 31;                                    \
            int gr = base + rr; if (gr >= n) gr = n - 1;                     \
            __pipeline_memcpy_async(dst + i,                                 \
                (const float4*)(x + (size_t)gr * FIN) + cc, 16);             \
        }                                                                    \
    } while (0)

    ISSUE_RAW(blockIdx.x, 0);
    __pipeline_commit();

    int wid = tid >> 5;
    int wm = wid >> 1;            // 16-row m-tile
    int nh = wid & 1;             // 64-col half
    int r = tid >> 2, q = tid & 3;

    int buf = 0;
    for (int tile = blockIdx.x; tile < ntiles; tile += gridDim.x) {
        int nextTile = tile + gridDim.x;
        if (nextTile < ntiles) {
            ISSUE_RAW(nextTile, buf ^ 1);
            __pipeline_commit();
            __pipeline_wait_prior(1);   // wait current tile's group (and B on iter 0)
        } else {
            __pipeline_wait_prior(0);
        }
        __syncthreads();                // all threads' raw data visible

        // convert raw -> A hi/lo (scale by dinv)
        {
            int gr = tile * 64 + r; if (gr >= n) gr = n - 1;
            float di = g_dinv[gr];
            const float4* raw = (const float4*)(smem + (buf ? OFF1_RAW1 : OFF1_RAW0))
                                + r * 32 + q * 8;
            char* rowh = smem + OFF1_AH + r * (LDA * 2) + q * 64;
            char* rowl = smem + OFF1_AL + r * (LDA * 2) + q * 64;
            #pragma unroll
            for (int j = 0; j < 4; j++) {
                float4 v0 = raw[j * 2], v1 = raw[j * 2 + 1];
                v0.x *= di; v0.y *= di; v0.z *= di; v0.w *= di;
                v1.x *= di; v1.y *= di; v1.z *= di; v1.w *= di;
                uint4 hi, lo;
                split8(v0, v1, &hi, &lo);
                *(uint4*)(rowh + j * 16) = hi;
                *(uint4*)(rowl + j * 16) = lo;
            }
        }
        __syncthreads();

        // MMA 64x128
        wmma::fragment<wmma::accumulator, 16, 16, 16, float> fc[4];
        #pragma unroll
        for (int nt = 0; nt < 4; nt++) wmma::fill_fragment(fc[nt], 0.f);
        const __nv_bfloat16* Ah = (const __nv_bfloat16*)(smem + OFF1_AH) + wm * 16 * LDA;
        const __nv_bfloat16* Al = (const __nv_bfloat16*)(smem + OFF1_AL) + wm * 16 * LDA;
        const __nv_bfloat16* Bh = (const __nv_bfloat16*)(smem + OFF1_BH) + nh * 64;
        const __nv_bfloat16* Bl = (const __nv_bfloat16*)(smem + OFF1_BL) + nh * 64;
        #pragma unroll
        for (int ks = 0; ks < 8; ks++) {
            wmma::fragment<wmma::matrix_a, 16, 16, 16, __nv_bfloat16, wmma::row_major> fah, fal;
            wmma::load_matrix_sync(fah, Ah + ks * 16, LDA);
            wmma::load_matrix_sync(fal, Al + ks * 16, LDA);
            #pragma unroll
            for (int nt = 0; nt < 4; nt++) {
                wmma::fragment<wmma::matrix_b, 16, 16, 16, __nv_bfloat16, wmma::row_major> fbh, fbl;
                wmma::load_matrix_sync(fbh, Bh + ks * 16 * LDA + nt * 16, LDA);
                wmma::load_matrix_sync(fbl, Bl + ks * 16 * LDA + nt * 16, LDA);
                wmma::mma_sync(fc[nt], fah, fbh, fc[nt]);
                wmma::mma_sync(fc[nt], fal, fbh, fc[nt]);
                wmma::mma_sync(fc[nt], fah, fbl, fc[nt]);
            }
        }
        float* yout = (float*)g_y4;
        #pragma unroll
        for (int nt = 0; nt < 4; nt++)
            wmma::store_matrix_sync(yout + (size_t)(tile * 64 + wm * 16) * FH + nh * 64 + nt * 16,
                                    fc[nt], FH, wmma::mem_row_major);
        __syncthreads();                // A buffer reusable next iter
        buf ^= 1;
    }
    #undef ISSUE_RAW
}

// ---------------- scans / scatter ----------------
__global__ void scan_block_kernel(int n) {
    __shared__ int s[512];
    int t = threadIdx.x;
    int i = blockIdx.x * 512 + t;
    int v = (i < n) ? g_deg[i] : 0;
    s[t] = v;
    __syncthreads();
    #pragma unroll
    for (int off = 1; off < 512; off <<= 1) {
        int u = (t >= off) ? s[t - off] : 0;
        __syncthreads();
        s[t] += u;
        __syncthreads();
    }
    if (i < n) g_rowstart[i] = s[t] - v;
    if (t == 511) g_bsums[blockIdx.x] = s[511];
}

__global__ void scan_top_kernel(int nb) {
    __shared__ int s[256];
    int t = threadIdx.x;
    int v = (t < nb) ? g_bsums[t] : 0;
    s[t] = v;
    __syncthreads();
    #pragma unroll
    for (int off = 1; off < 256; off <<= 1) {
        int u = (t >= off) ? s[t - off] : 0;
        __syncthreads();
        s[t] += u;
        __syncthreads();
    }
    if (t < nb) g_bsums[t] = s[t] - v;
}

__global__ void scan_add_kernel(int n) {
    int i = blockIdx.x * 512 + threadIdx.x;
    if (i < n) g_rowstart[i] += g_bsums[blockIdx.x];
}

__global__ void scatter_kernel(const void* __restrict__ ei, int E) {
    int e = blockIdx.x * blockDim.x + threadIdx.x;
    if (e < E) {
        int d = load_node(ei, (size_t)E + e);
        int s = load_node(ei, (size_t)e);
        int p = atomicAdd(&g_cursor[d], 1);
        g_adj[g_rowstart[d] + p] = s;
    }
}

// ---------------- agg1: h' = relu(dinv*(sum+self)+b1)*dinv, bf16 hi/lo out ----------------
__global__ __launch_bounds__(256) void agg1_kernel(const float* __restrict__ b1, int n) {
    int gw = (blockIdx.x * blockDim.x + threadIdx.x) >> 5;
    int lane = threadIdx.x & 31;
    if (gw >= n) return;
    float4 acc = g_y4[(size_t)gw * 32 + lane];
    float4 acc2 = make_float4(0.f, 0.f, 0.f, 0.f);
    int s0 = g_rowstart[gw];
    int d  = g_deg[gw];
    int j = 0;
    for (; j + 1 < d; j += 2) {
        int sa = g_adj[s0 + j];
        int sb = g_adj[s0 + j + 1];
        float4 va = g_y4[(size_t)sa * 32 + lane];
        float4 vb = g_y4[(size_t)sb * 32 + lane];
        acc.x += va.x;  acc.y += va.y;  acc.z += va.z;  acc.w += va.w;
        acc2.x += vb.x; acc2.y += vb.y; acc2.z += vb.z; acc2.w += vb.w;
    }
    if (j < d) {
        int sa = g_adj[s0 + j];
        float4 va = g_y4[(size_t)sa * 32 + lane];
        acc.x += va.x; acc.y += va.y; acc.z += va.z; acc.w += va.w;
    }
    acc.x += acc2.x; acc.y += acc2.y; acc.z += acc2.z; acc.w += acc2.w;
    float di = g_dinv[gw];
    float4 bb = ((const float4*)b1)[lane];
    float4 o;
    o.x = fmaxf(fmaf(acc.x, di, bb.x), 0.f) * di;
    o.y = fmaxf(fmaf(acc.y, di, bb.y), 0.f) * di;
    o.z = fmaxf(fmaf(acc.z, di, bb.z), 0.f) * di;
    o.w = fmaxf(fmaf(acc.w, di, bb.w), 0.f) * di;
    __nv_bfloat16 hx = __float2bfloat16_rn(o.x), hy = __float2bfloat16_rn(o.y);
    __nv_bfloat16 hz = __float2bfloat16_rn(o.z), hw = __float2bfloat16_rn(o.w);
    uint2 hiw, low;
    hiw.x = ((uint32_t)__bfloat16_as_ushort(hy) << 16) | __bfloat16_as_ushort(hx);
    hiw.y = ((uint32_t)__bfloat16_as_ushort(hw) << 16) | __bfloat16_as_ushort(hz);
    low.x = pack_bf16x2(o.x - __bfloat162float(hx), o.y - __bfloat162float(hy));
    low.y = pack_bf16x2(o.z - __bfloat162float(hz), o.w - __bfloat162float(hw));
    ((uint2*)g_hh)[(size_t)gw * 32 + lane] = hiw;
    ((uint2*)g_hl)[(size_t)gw * 32 + lane] = low;
}

// ---------------- GEMM2: z = h' @ W2 (wmma bf16 3-term, N=48) ----------------
__global__ void __launch_bounds__(256) gemm2_wmma_kernel(int n) {
    extern __shared__ char smem[];
    int tid = threadIdx.x;
    int r0 = blockIdx.x * 128;

    {
        float4* dbh = (float4*)(smem + OFF2_BH);
        float4* dbl = (float4*)(smem + OFF2_BL);
        for (int i = tid; i < W2_IMG_F4; i += 256) {
            __pipeline_memcpy_async(dbh + i, g_W2h4 + i, 16);
            __pipeline_memcpy_async(dbl + i, g_W2l4 + i, 16);
        }
    }
    {
        int r = tid >> 1, q = tid & 1;
        int gr = r0 + r; if (gr >= n) gr = n - 1;
        const uint4* sh = g_hh + (size_t)gr * 16 + q * 8;
        const uint4* sl = g_hl + (size_t)gr * 16 + q * 8;
        char* rowh = smem + OFF2_AH + r * (LDA * 2) + q * 128;
        char* rowl = smem + OFF2_AL + r * (LDA * 2) + q * 128;
        #pragma unroll
        for (int j = 0; j < 8; j++) {
            __pipeline_memcpy_async(rowh + j * 16, sh + j, 16);
            __pipeline_memcpy_async(rowl + j * 16, sl + j, 16);
        }
    }
    __pipeline_commit();
    __pipeline_wait_prior(0);
    __syncthreads();

    int w = tid >> 5;
    wmma::fragment<wmma::accumulator, 16, 16, 16, float> fc[3];
    #pragma unroll
    for (int nt = 0; nt < 3; nt++) wmma::fill_fragment(fc[nt], 0.f);

    const __nv_bfloat16* Ah = (const __nv_bfloat16*)(smem + OFF2_AH) + w * 16 * LDA;
    const __nv_bfloat16* Al = (const __nv_bfloat16*)(smem + OFF2_AL) + w * 16 * LDA;
    const __nv_bfloat16* Bh = (const __nv_bfloat16*)(smem + OFF2_BH);
    const __nv_bfloat16* Bl = (const __nv_bfloat16*)(smem + OFF2_BL);

    #pragma unroll
    for (int ks = 0; ks < 8; ks++) {
        wmma::fragment<wmma::matrix_a, 16, 16, 16, __nv_bfloat16, wmma::row_major> fah, fal;
        wmma::load_matrix_sync(fah, Ah + ks * 16, LDA);
        wmma::load_matrix_sync(fal, Al + ks * 16, LDA);
        #pragma unroll
        for (int nt = 0; nt < 3; nt++) {
            wmma::fragment<wmma::matrix_b, 16, 16, 16, __nv_bfloat16, wmma::row_major> fbh, fbl;
            wmma::load_matrix_sync(fbh, Bh + ks * 16 * LDB2 + nt * 16, LDB2);
            wmma::load_matrix_sync(fbl, Bl + ks * 16 * LDB2 + nt * 16, LDB2);
            wmma::mma_sync(fc[nt], fah, fbh, fc[nt]);
            wmma::mma_sync(fc[nt], fal, fbh, fc[nt]);
            wmma::mma_sync(fc[nt], fah, fbl, fc[nt]);
        }
    }

    float* zout = (float*)g_z4;
    #pragma unroll
    for (int nt = 0; nt < 3; nt++)
        wmma::store_matrix_sync(zout + (size_t)(r0 + w * 16) * FCP + nt * 16, fc[nt], FCP,
                                wmma::mem_row_major);
}

// ---------------- agg2 + log_softmax (2 nodes per warp, z stride 48) ----------------
__global__ __launch_bounds__(256) void agg2_kernel(const float* __restrict__ b2,
                                                   float* __restrict__ out, int n) {
    int warp = (blockIdx.x * blockDim.x + threadIdx.x) >> 5;
    int lane = threadIdx.x & 31;
    int half = lane >> 4;
    int hl = lane & 15;
    int node = warp * 2 + half;
    bool valid = (node < n);
    bool act = valid && (hl < 10);
    float4 acc = make_float4(0.f, 0.f, 0.f, 0.f);
    if (act) acc = g_z4[(size_t)node * 12 + hl];
    int s0 = valid ? g_rowstart[node] : 0;
    int d  = valid ? g_deg[node] : 0;
    for (int j = 0; j < d; j++) {
        int s = g_adj[s0 + j];
        if (act) {
            float4 v = g_z4[(size_t)s * 12 + hl];
            acc.x += v.x; acc.y += v.y; acc.z += v.z; acc.w += v.w;
        }
    }
    float di = valid ? g_dinv[node] : 0.f;
    float4 l = make_float4(-INFINITY, -INFINITY, -INFINITY, -INFINITY);
    if (act) {
        float4 bb = *(const float4*)&b2[hl * 4];
        l.x = fmaf(acc.x, di, bb.x);
        l.y = fmaf(acc.y, di, bb.y);
        l.z = fmaf(acc.z, di, bb.z);
        l.w = fmaf(acc.w, di, bb.w);
    }
    float m = fmaxf(fmaxf(l.x, l.y), fmaxf(l.z, l.w));
    #pragma unroll
    for (int off = 8; off >= 1; off >>= 1)
        m = fmaxf(m, __shfl_xor_sync(0xffffffffu, m, off));
    float ssum = 0.f;
    if (act)
        ssum = expf(l.x - m) + expf(l.y - m) + expf(l.z - m) + expf(l.w - m);
    #pragma unroll
    for (int off = 8; off >= 1; off >>= 1)
        ssum += __shfl_xor_sync(0xffffffffu, ssum, off);
    float lse = m + logf(ssum);
    if (act) {
        float4 o;
        o.x = l.x - lse; o.y = l.y - lse; o.z = l.z - lse; o.w = l.w - lse;
        *(float4*)&out[(size_t)node * FC + hl * 4] = o;
    }
}

// ---------------- launch ----------------
extern "C" void kernel_launch(void* const* d_in, const int* in_sizes, int n_in,
                              void* d_out, int out_size) {
    const float* x  = (const float*)d_in[0];
    const void*  ei = d_in[1];
    const float* W1 = (const float*)d_in[2];
    const float* b1 = (const float*)d_in[3];
    const float* W2 = (const float*)d_in[4];
    const float* b2 = (const float*)d_in[5];
    float* out = (float*)d_out;

    int n = in_sizes[0] / FIN;   // 100000
    int E = in_sizes[1] / 2;     // 640000
    int NB = (n + 511) / 512;
    int ntiles = (n + 63) / 64;

    static cudaStream_t s2 = nullptr;
    static cudaEvent_t eFork = nullptr, eJoin = nullptr;
    static int init_done = 0;
    if (!init_done) {
        cudaFuncSetAttribute(gemm1_wmma_kernel,
                             cudaFuncAttributeMaxDynamicSharedMemorySize, SM1_TOTAL);
        cudaFuncSetAttribute(gemm2_wmma_kernel,
                             cudaFuncAttributeMaxDynamicSharedMemorySize, SM2_TOTAL);
        cudaStreamCreateWithFlags(&s2, cudaStreamNonBlocking);
        cudaEventCreateWithFlags(&eFork, cudaEventDisableTiming);
        cudaEventCreateWithFlags(&eJoin, cudaEventDisableTiming);
        init_done = 1;
    }

    // serial prologue
    zdetect_kernel<<<(n + 255) / 256, 256>>>((const int*)ei, 2 * E, n);
    hist_kernel<<<(E + 255) / 256, 256>>>(ei, E);

    // fork: CSR chain on s2 runs concurrently with dinv_prep + gemm1
    cudaEventRecord(eFork, 0);
    cudaStreamWaitEvent(s2, eFork, 0);

    scan_block_kernel<<<NB, 512, 0, s2>>>(n);
    scan_top_kernel<<<1, 256, 0, s2>>>(NB);
    scan_add_kernel<<<NB, 512, 0, s2>>>(n);
    scatter_kernel<<<(E + 255) / 256, 256, 0, s2>>>(ei, E);
    cudaEventRecord(eJoin, s2);

    dinv_prep_kernel<<<(n + 255) / 256, 256>>>(W1, W2, n);
    gemm1_wmma_kernel<<<148, 256, SM1_TOTAL>>>(x, n, ntiles);

    // join before aggregation (needs CSR + y)
    cudaStreamWaitEvent(0, eJoin, 0);

    agg1_kernel<<<(n * 32 + 255) / 256, 256>>>(b1, n);
    gemm2_wmma_kernel<<<(n + 127) / 128, 256, SM2_TOTAL>>>(n);
    int warps2 = (n + 1) / 2;
    agg2_kernel<<<(warps2 * 32 + 255) / 256, 256>>>(b2, out, n);
}

// round 16
// speedup vs baseline: 1.3006x; 1.0149x over previous
#include <cuda_runtime.h>
#include <cuda_bf16.h>
#include <cuda_pipeline.h>
#include <mma.h>
#include <math.h>
#include <stdint.h>

using namespace nvcuda;

// Problem constants (DebugGCN: N=100000 nodes, E=640000 edges, 128->128->40)
#define NMAX 100000
#define EMAX 640000
#define FIN 128
#define FH  128
#define FC  40
#define FCP 48

// ---- gemm1: 128 rows/block, 512 threads, ld=136 (272B stride, LDSM conflict-free)
#define G1_ROWS 128
#define LDA 136
#define OFF_AH 0
#define OFF_AL 34816          // 128*136*2
#define OFF_BH 69632
#define OFF_BL 104448
#define SM1_TOTAL 139264
#define W1_IMG_F4 2176        // 128*136*2/16

// ---- gemm2: 128 rows/block, A ld=136, B ld=72 (144B stride, conflict-free)
#define LDB2 72
#define OFF2_AH 0
#define OFF2_AL 34816
#define OFF2_BH 69632
#define OFF2_BL 88064
#define SM2_TOTAL 106496
#define W2_IMG_F4 1152

// -------- scratch (device globals) --------
__device__ float4 g_y4[(size_t)(NMAX + 128) * (FH / 4)];   // dinv*(x@W1)
__device__ uint4  g_hh[(size_t)(NMAX + 128) * 16];         // h' hi bf16 rows
__device__ uint4  g_hl[(size_t)(NMAX + 128) * 16];         // h' lo
__device__ float4 g_z4[(size_t)(NMAX + 128) * (FCP / 4)];  // h'@W2 (padded 48)
__device__ float  g_dinv[NMAX];
__device__ int    g_deg[NMAX];
__device__ int    g_cursor[NMAX];
__device__ int    g_rowstart[NMAX];
__device__ int    g_adj[EMAX];
__device__ int    g_bsums[512];
__device__ int    g_is64;
__device__ float4 g_W1h4[W1_IMG_F4];
__device__ float4 g_W1l4[W1_IMG_F4];
__device__ float4 g_W2h4[W2_IMG_F4];
__device__ float4 g_W2l4[W2_IMG_F4];

__device__ __forceinline__ uint32_t pack_bf16x2(float a, float b) {
    __nv_bfloat16 ha = __float2bfloat16_rn(a);
    __nv_bfloat16 hb = __float2bfloat16_rn(b);
    return ((uint32_t)__bfloat16_as_ushort(hb) << 16) | __bfloat16_as_ushort(ha);
}
__device__ __forceinline__ void split8(float4 v0, float4 v1, uint4* hi, uint4* lo) {
    float f[8] = {v0.x, v0.y, v0.z, v0.w, v1.x, v1.y, v1.z, v1.w};
    uint32_t hw[4], lw[4];
    #pragma unroll
    for (int p = 0; p < 4; p++) {
        float a = f[2 * p], b = f[2 * p + 1];
        __nv_bfloat16 ha = __float2bfloat16_rn(a);
        __nv_bfloat16 hb = __float2bfloat16_rn(b);
        hw[p] = ((uint32_t)__bfloat16_as_ushort(hb) << 16) | __bfloat16_as_ushort(ha);
        lw[p] = pack_bf16x2(a - __bfloat162float(ha), b - __bfloat162float(hb));
    }
    *hi = *(uint4*)hw; *lo = *(uint4*)lw;
}

// ---------------- merged zero + edge-dtype detect ----------------
__global__ void zdetect_kernel(const int* __restrict__ ei32, int words, int n) {
    int i = blockIdx.x * blockDim.x + threadIdx.x;
    if (i < n) { g_deg[i] = 0; g_cursor[i] = 0; }
    if (blockIdx.x == 0) {
        __shared__ int flag;
        if (threadIdx.x == 0) flag = 0;
        __syncthreads();
        int acc = 0;
        for (int j = threadIdx.x * 2 + 1; j < words; j += 2 * 256 * 16) acc |= ei32[j];
        if (acc) atomicOr(&flag, 1);
        __syncthreads();
        if (threadIdx.x == 0) g_is64 = (flag == 0) ? 1 : 0;
    }
}

__device__ __forceinline__ int load_node(const void* ei, size_t idx) {
    if (g_is64) return (int)((const long long*)ei)[idx];
    return ((const int*)ei)[idx];
}

__global__ void hist_kernel(const void* __restrict__ ei, int E) {
    int e = blockIdx.x * blockDim.x + threadIdx.x;
    if (e < E) atomicAdd(&g_deg[load_node(ei, (size_t)E + e)], 1);
}

// ---------------- dinv + W1/W2 hi-lo split prep ----------------
__global__ void dinv_prep_kernel(const float* __restrict__ W1,
                                 const float* __restrict__ W2, int n) {
    int i = blockIdx.x * blockDim.x + threadIdx.x;
    if (i < n) g_dinv[i] = rsqrtf((float)(g_deg[i] + 1));
    if (i < FIN * FH) {
        int k = i >> 7, c = i & 127;
        float w = W1[i];
        __nv_bfloat16 h = __float2bfloat16_rn(w);
        __nv_bfloat16 l = __float2bfloat16_rn(w - __bfloat162float(h));
        ((__nv_bfloat16*)g_W1h4)[k * LDA + c] = h;
        ((__nv_bfloat16*)g_W1l4)[k * LDA + c] = l;
    }
    if (i < FIN * 8) {
        int k = i >> 3, c = 128 + (i & 7);
        ((__nv_bfloat16*)g_W1h4)[k * LDA + c] = __float2bfloat16_rn(0.f);
        ((__nv_bfloat16*)g_W1l4)[k * LDA + c] = __float2bfloat16_rn(0.f);
    }
    if (i < FH * LDB2) {
        int k = i / LDB2, c = i % LDB2;
        float w = (c < FC) ? W2[k * FC + c] : 0.f;
        __nv_bfloat16 h = __float2bfloat16_rn(w);
        __nv_bfloat16 l = __float2bfloat16_rn(w - __bfloat162float(h));
        ((__nv_bfloat16*)g_W2h4)[k * LDB2 + c] = h;
        ((__nv_bfloat16*)g_W2l4)[k * LDB2 + c] = l;
    }
}

// ---------------- GEMM1: y = (dinv.x) @ W1, 512 threads, 16 warps x 4 tiles ----------------
__global__ void __launch_bounds__(512) gemm1_wmma_kernel(const float* __restrict__ x, int n) {
    extern __shared__ char smem[];
    int tid = threadIdx.x;
    int r0 = blockIdx.x * G1_ROWS;

    // async-copy W1 hi/lo images into smem
    {
        float4* dbh = (float4*)(smem + OFF_BH);
        float4* dbl = (float4*)(smem + OFF_BL);
        for (int i = tid; i < W1_IMG_F4; i += 512) {
            __pipeline_memcpy_async(dbh + i, g_W1h4 + i, 16);
            __pipeline_memcpy_async(dbl + i, g_W1l4 + i, 16);
        }
        __pipeline_commit();
    }

    // stage A: 128 rows, 4 threads/row (32 feats each); scale by dinv, split hi/lo
    {
        int r = tid >> 2, q = tid & 3;
        int gr = r0 + r; if (gr >= n) gr = n - 1;
        float di = g_dinv[gr];
        const float4* xr = (const float4*)(x + (size_t)gr * FIN) + q * 8;
        char* rowh = smem + OFF_AH + r * (LDA * 2) + q * 64;
        char* rowl = smem + OFF_AL + r * (LDA * 2) + q * 64;
        #pragma unroll
        for (int j = 0; j < 4; j++) {
            float4 v0 = xr[j * 2], v1 = xr[j * 2 + 1];
            v0.x *= di; v0.y *= di; v0.z *= di; v0.w *= di;
            v1.x *= di; v1.y *= di; v1.z *= di; v1.w *= di;
            uint4 hi, lo;
            split8(v0, v1, &hi, &lo);
            *(uint4*)(rowh + j * 16) = hi;
            *(uint4*)(rowl + j * 16) = lo;
        }
    }
    __pipeline_wait_prior(0);
    __syncthreads();

    // 16 warps: mt = wid>>1 covers ALL 8 m-tiles; nh = wid&1 the 64-col half;
    // 4 n-tile fragments per warp -> 8*2*4 = 64 tiles = full 128x128 block tile.
    int wid = tid >> 5;
    int mt = wid >> 1;            // 0..7 (16-row m-tile)
    int nh = wid & 1;             // 0..1 (64-col half)

    wmma::fragment<wmma::accumulator, 16, 16, 16, float> fc[4];
    #pragma unroll
    for (int nt = 0; nt < 4; nt++) wmma::fill_fragment(fc[nt], 0.f);

    const __nv_bfloat16* Ah = (const __nv_bfloat16*)(smem + OFF_AH) + mt * 16 * LDA;
    const __nv_bfloat16* Al = (const __nv_bfloat16*)(smem + OFF_AL) + mt * 16 * LDA;
    const __nv_bfloat16* Bh = (const __nv_bfloat16*)(smem + OFF_BH) + nh * 64;
    const __nv_bfloat16* Bl = (const __nv_bfloat16*)(smem + OFF_BL) + nh * 64;

    #pragma unroll
    for (int ks = 0; ks < 8; ks++) {
        wmma::fragment<wmma::matrix_a, 16, 16, 16, __nv_bfloat16, wmma::row_major> fah, fal;
        wmma::load_matrix_sync(fah, Ah + ks * 16, LDA);
        wmma::load_matrix_sync(fal, Al + ks * 16, LDA);
        #pragma unroll
        for (int nt = 0; nt < 4; nt++) {
            wmma::fragment<wmma::matrix_b, 16, 16, 16, __nv_bfloat16, wmma::row_major> fbh, fbl;
            wmma::load_matrix_sync(fbh, Bh + ks * 16 * LDA + nt * 16, LDA);
            wmma::load_matrix_sync(fbl, Bl + ks * 16 * LDA + nt * 16, LDA);
            wmma::mma_sync(fc[nt], fah, fbh, fc[nt]);
            wmma::mma_sync(fc[nt], fal, fbh, fc[nt]);
            wmma::mma_sync(fc[nt], fah, fbl, fc[nt]);
        }
    }

    float* yout = (float*)g_y4;
    #pragma unroll
    for (int nt = 0; nt < 4; nt++)
        wmma::store_matrix_sync(yout + (size_t)(r0 + mt * 16) * FH + nh * 64 + nt * 16,
                                fc[nt], FH, wmma::mem_row_major);
}

// ---------------- scans / scatter ----------------
__global__ void scan_block_kernel(int n) {
    __shared__ int s[512];
    int t = threadIdx.x;
    int i = blockIdx.x * 512 + t;
    int v = (i < n) ? g_deg[i] : 0;
    s[t] = v;
    __syncthreads();
    #pragma unroll
    for (int off = 1; off < 512; off <<= 1) {
        int u = (t >= off) ? s[t - off] : 0;
        __syncthreads();
        s[t] += u;
        __syncthreads();
    }
    if (i < n) g_rowstart[i] = s[t] - v;
    if (t == 511) g_bsums[blockIdx.x] = s[511];
}

__global__ void scan_top_kernel(int nb) {
    __shared__ int s[256];
    int t = threadIdx.x;
    int v = (t < nb) ? g_bsums[t] : 0;
    s[t] = v;
    __syncthreads();
    #pragma unroll
    for (int off = 1; off < 256; off <<= 1) {
        int u = (t >= off) ? s[t - off] : 0;
        __syncthreads();
        s[t] += u;
        __syncthreads();
    }
    if (t < nb) g_bsums[t] = s[t] - v;
}

__global__ void scan_add_kernel(int n) {
    int i = blockIdx.x * 512 + threadIdx.x;
    if (i < n) g_rowstart[i] += g_bsums[blockIdx.x];
}

__global__ void scatter_kernel(const void* __restrict__ ei, int E) {
    int e = blockIdx.x * blockDim.x + threadIdx.x;
    if (e < E) {
        int d = load_node(ei, (size_t)E + e);
        int s = load_node(ei, (size_t)e);
        int p = atomicAdd(&g_cursor[d], 1);
        g_adj[g_rowstart[d] + p] = s;
    }
}

// ---------------- agg1: h' = relu(dinv*(sum+self)+b1)*dinv, bf16 hi/lo out ----------------
__global__ __launch_bounds__(256) void agg1_kernel(const float* __restrict__ b1, int n) {
    int gw = (blockIdx.x * blockDim.x + threadIdx.x) >> 5;
    int lane = threadIdx.x & 31;
    if (gw >= n) return;
    float4 acc = g_y4[(size_t)gw * 32 + lane];
    float4 acc2 = make_float4(0.f, 0.f, 0.f, 0.f);
    int s0 = g_rowstart[gw];
    int d  = g_deg[gw];
    int j = 0;
    for (; j + 1 < d; j += 2) {
        int sa = g_adj[s0 + j];
        int sb = g_adj[s0 + j + 1];
        float4 va = g_y4[(size_t)sa * 32 + lane];
        float4 vb = g_y4[(size_t)sb * 32 + lane];
        acc.x += va.x;  acc.y += va.y;  acc.z += va.z;  acc.w += va.w;
        acc2.x += vb.x; acc2.y += vb.y; acc2.z += vb.z; acc2.w += vb.w;
    }
    if (j < d) {
        int sa = g_adj[s0 + j];
        float4 va = g_y4[(size_t)sa * 32 + lane];
        acc.x += va.x; acc.y += va.y; acc.z += va.z; acc.w += va.w;
    }
    acc.x += acc2.x; acc.y += acc2.y; acc.z += acc2.z; acc.w += acc2.w;
    float di = g_dinv[gw];
    float4 bb = ((const float4*)b1)[lane];
    float4 o;
    o.x = fmaxf(fmaf(acc.x, di, bb.x), 0.f) * di;
    o.y = fmaxf(fmaf(acc.y, di, bb.y), 0.f) * di;
    o.z = fmaxf(fmaf(acc.z, di, bb.z), 0.f) * di;
    o.w = fmaxf(fmaf(acc.w, di, bb.w), 0.f) * di;
    __nv_bfloat16 hx = __float2bfloat16_rn(o.x), hy = __float2bfloat16_rn(o.y);
    __nv_bfloat16 hz = __float2bfloat16_rn(o.z), hw = __float2bfloat16_rn(o.w);
    uint2 hiw, low;
    hiw.x = ((uint32_t)__bfloat16_as_ushort(hy) << 16) | __bfloat16_as_ushort(hx);
    hiw.y = ((uint32_t)__bfloat16_as_ushort(hw) << 16) | __bfloat16_as_ushort(hz);
    low.x = pack_bf16x2(o.x - __bfloat162float(hx), o.y - __bfloat162float(hy));
    low.y = pack_bf16x2(o.z - __bfloat162float(hz), o.w - __bfloat162float(hw));
    ((uint2*)g_hh)[(size_t)gw * 32 + lane] = hiw;
    ((uint2*)g_hl)[(size_t)gw * 32 + lane] = low;
}

// ---------------- GEMM2: z = h' @ W2 (wmma bf16 3-term, N=48) ----------------
__global__ void __launch_bounds__(256) gemm2_wmma_kernel(int n) {
    extern __shared__ char smem[];
    int tid = threadIdx.x;
    int r0 = blockIdx.x * 128;

    {
        float4* dbh = (float4*)(smem + OFF2_BH);
        float4* dbl = (float4*)(smem + OFF2_BL);
        for (int i = tid; i < W2_IMG_F4; i += 256) {
            __pipeline_memcpy_async(dbh + i, g_W2h4 + i, 16);
            __pipeline_memcpy_async(dbl + i, g_W2l4 + i, 16);
        }
    }
    {
        int r = tid >> 1, q = tid & 1;
        int gr = r0 + r; if (gr >= n) gr = n - 1;
        const uint4* sh = g_hh + (size_t)gr * 16 + q * 8;
        const uint4* sl = g_hl + (size_t)gr * 16 + q * 8;
        char* rowh = smem + OFF2_AH + r * (LDA * 2) + q * 128;
        char* rowl = smem + OFF2_AL + r * (LDA * 2) + q * 128;
        #pragma unroll
        for (int j = 0; j < 8; j++) {
            __pipeline_memcpy_async(rowh + j * 16, sh + j, 16);
            __pipeline_memcpy_async(rowl + j * 16, sl + j, 16);
        }
    }
    __pipeline_commit();
    __pipeline_wait_prior(0);
    __syncthreads();

    int w = tid >> 5;
    wmma::fragment<wmma::accumulator, 16, 16, 16, float> fc[3];
    #pragma unroll
    for (int nt = 0; nt < 3; nt++) wmma::fill_fragment(fc[nt], 0.f);

    const __nv_bfloat16* Ah = (const __nv_bfloat16*)(smem + OFF2_AH) + w * 16 * LDA;
    const __nv_bfloat16* Al = (const __nv_bfloat16*)(smem + OFF2_AL) + w * 16 * LDA;
    const __nv_bfloat16* Bh = (const __nv_bfloat16*)(smem + OFF2_BH);
    const __nv_bfloat16* Bl = (const __nv_bfloat16*)(smem + OFF2_BL);

    #pragma unroll
    for (int ks = 0; ks < 8; ks++) {
        wmma::fragment<wmma::matrix_a, 16, 16, 16, __nv_bfloat16, wmma::row_major> fah, fal;
        wmma::load_matrix_sync(fah, Ah + ks * 16, LDA);
        wmma::load_matrix_sync(fal, Al + ks * 16, LDA);
        #pragma unroll
        for (int nt = 0; nt < 3; nt++) {
            wmma::fragment<wmma::matrix_b, 16, 16, 16, __nv_bfloat16, wmma::row_major> fbh, fbl;
            wmma::load_matrix_sync(fbh, Bh + ks * 16 * LDB2 + nt * 16, LDB2);
            wmma::load_matrix_sync(fbl, Bl + ks * 16 * LDB2 + nt * 16, LDB2);
            wmma::mma_sync(fc[nt], fah, fbh, fc[nt]);
            wmma::mma_sync(fc[nt], fal, fbh, fc[nt]);
            wmma::mma_sync(fc[nt], fah, fbl, fc[nt]);
        }
    }

    float* zout = (float*)g_z4;
    #pragma unroll
    for (int nt = 0; nt < 3; nt++)
        wmma::store_matrix_sync(zout + (size_t)(r0 + w * 16) * FCP + nt * 16, fc[nt], FCP,
                                wmma::mem_row_major);
}

// ---------------- agg2 + log_softmax (2 nodes per warp, z stride 48) ----------------
__global__ __launch_bounds__(256) void agg2_kernel(const float* __restrict__ b2,
                                                   float* __restrict__ out, int n) {
    int warp = (blockIdx.x * blockDim.x + threadIdx.x) >> 5;
    int lane = threadIdx.x & 31;
    int half = lane >> 4;
    int hl = lane & 15;
    int node = warp * 2 + half;
    bool valid = (node < n);
    bool act = valid && (hl < 10);
    float4 acc = make_float4(0.f, 0.f, 0.f, 0.f);
    if (act) acc = g_z4[(size_t)node * 12 + hl];
    int s0 = valid ? g_rowstart[node] : 0;
    int d  = valid ? g_deg[node] : 0;
    for (int j = 0; j < d; j++) {
        int s = g_adj[s0 + j];
        if (act) {
            float4 v = g_z4[(size_t)s * 12 + hl];
            acc.x += v.x; acc.y += v.y; acc.z += v.z; acc.w += v.w;
        }
    }
    float di = valid ? g_dinv[node] : 0.f;
    float4 l = make_float4(-INFINITY, -INFINITY, -INFINITY, -INFINITY);
    if (act) {
        float4 bb = *(const float4*)&b2[hl * 4];
        l.x = fmaf(acc.x, di, bb.x);
        l.y = fmaf(acc.y, di, bb.y);
        l.z = fmaf(acc.z, di, bb.z);
        l.w = fmaf(acc.w, di, bb.w);
    }
    float m = fmaxf(fmaxf(l.x, l.y), fmaxf(l.z, l.w));
    #pragma unroll
    for (int off = 8; off >= 1; off >>= 1)
        m = fmaxf(m, __shfl_xor_sync(0xffffffffu, m, off));
    float ssum = 0.f;
    if (act)
        ssum = expf(l.x - m) + expf(l.y - m) + expf(l.z - m) + expf(l.w - m);
    #pragma unroll
    for (int off = 8; off >= 1; off >>= 1)
        ssum += __shfl_xor_sync(0xffffffffu, ssum, off);
    float lse = m + logf(ssum);
    if (act) {
        float4 o;
        o.x = l.x - lse; o.y = l.y - lse; o.z = l.z - lse; o.w = l.w - lse;
        *(float4*)&out[(size_t)node * FC + hl * 4] = o;
    }
}

// ---------------- launch ----------------
extern "C" void kernel_launch(void* const* d_in, const int* in_sizes, int n_in,
                              void* d_out, int out_size) {
    const float* x  = (const float*)d_in[0];
    const void*  ei = d_in[1];
    const float* W1 = (const float*)d_in[2];
    const float* b1 = (const float*)d_in[3];
    const float* W2 = (const float*)d_in[4];
    const float* b2 = (const float*)d_in[5];
    float* out = (float*)d_out;

    int n = in_sizes[0] / FIN;   // 100000
    int E = in_sizes[1] / 2;     // 640000
    int NB = (n + 511) / 512;

    static cudaStream_t s2 = nullptr;
    static cudaEvent_t eFork = nullptr, eJoin = nullptr;
    static int init_done = 0;
    if (!init_done) {
        cudaFuncSetAttribute(gemm1_wmma_kernel,
                             cudaFuncAttributeMaxDynamicSharedMemorySize, SM1_TOTAL);
        cudaFuncSetAttribute(gemm2_wmma_kernel,
                             cudaFuncAttributeMaxDynamicSharedMemorySize, SM2_TOTAL);
        cudaStreamCreateWithFlags(&s2, cudaStreamNonBlocking);
        cudaEventCreateWithFlags(&eFork, cudaEventDisableTiming);
        cudaEventCreateWithFlags(&eJoin, cudaEventDisableTiming);
        init_done = 1;
    }

    // serial prologue
    zdetect_kernel<<<(n + 255) / 256, 256>>>((const int*)ei, 2 * E, n);
    hist_kernel<<<(E + 255) / 256, 256>>>(ei, E);

    // fork: CSR chain on s2 runs concurrently with dinv_prep + gemm1
    cudaEventRecord(eFork, 0);
    cudaStreamWaitEvent(s2, eFork, 0);

    scan_block_kernel<<<NB, 512, 0, s2>>>(n);
    scan_top_kernel<<<1, 256, 0, s2>>>(NB);
    scan_add_kernel<<<NB, 512, 0, s2>>>(n);
    scatter_kernel<<<(E + 255) / 256, 256, 0, s2>>>(ei, E);
    cudaEventRecord(eJoin, s2);

    dinv_prep_kernel<<<(n + 255) / 256, 256>>>(W1, W2, n);
    gemm1_wmma_kernel<<<(n + G1_ROWS - 1) / G1_ROWS, 512, SM1_TOTAL>>>(x, n);

    // join before aggregation (needs CSR + y)
    cudaStreamWaitEvent(0, eJoin, 0);

    agg1_kernel<<<(n * 32 + 255) / 256, 256>>>(b1, n);
    gemm2_wmma_kernel<<<(n + 127) / 128, 256, SM2_TOTAL>>>(n);
    int warps2 = (n + 1) / 2;
    agg2_kernel<<<(warps2 * 32 + 255) / 256, 256>>>(b2, out, n);
}

// round 17
// speedup vs baseline: 1.3264x; 1.0198x over previous
#include <cuda_runtime.h>
#include <cuda_bf16.h>
#include <cuda_pipeline.h>
#include <mma.h>
#include <math.h>
#include <stdint.h>

using namespace nvcuda;

// Problem constants (DebugGCN: N=100000 nodes, E=640000 edges, 128->128->40)
#define NMAX 100000
#define EMAX 640000
#define FIN 128
#define FH  128
#define FC  40
#define FCP 48

// ---- gemm1: 128 rows/block, 256 threads, ld=136 (272B stride, LDSM conflict-free)
#define G1_ROWS 128
#define LDA 136
#define OFF_AH 0
#define OFF_AL 34816          // 128*136*2
#define OFF_BH 69632
#define OFF_BL 104448
#define SM1_TOTAL 139264
#define W1_IMG_F4 2176        // 128*136*2/16

// ---- gemm2: 128 rows/block, A ld=136, B ld=72 (144B stride, conflict-free)
#define LDB2 72
#define OFF2_AH 0
#define OFF2_AL 34816
#define OFF2_BH 69632
#define OFF2_BL 88064
#define SM2_TOTAL 106496
#define W2_IMG_F4 1152

// -------- scratch (device globals) --------
__device__ float4 g_y4[(size_t)(NMAX + 128) * (FH / 4)];   // x@W1 (UNscaled)
__device__ uint4  g_hh[(size_t)(NMAX + 128) * 16];         // h' hi bf16 rows
__device__ uint4  g_hl[(size_t)(NMAX + 128) * 16];         // h' lo
__device__ float4 g_z4[(size_t)(NMAX + 128) * (FCP / 4)];  // h'@W2 (padded 48)
__device__ float  g_dinv[NMAX];
__device__ int    g_deg[NMAX];
__device__ int    g_cursor[NMAX];
__device__ int    g_rowstart[NMAX];
__device__ int    g_adj[EMAX];
__device__ int    g_bsums[512];
__device__ int    g_is64;
__device__ float4 g_W1h4[W1_IMG_F4];
__device__ float4 g_W1l4[W1_IMG_F4];
__device__ float4 g_W2h4[W2_IMG_F4];
__device__ float4 g_W2l4[W2_IMG_F4];

__device__ __forceinline__ uint32_t pack_bf16x2(float a, float b) {
    __nv_bfloat16 ha = __float2bfloat16_rn(a);
    __nv_bfloat16 hb = __float2bfloat16_rn(b);
    return ((uint32_t)__bfloat16_as_ushort(hb) << 16) | __bfloat16_as_ushort(ha);
}
__device__ __forceinline__ void split8(float4 v0, float4 v1, uint4* hi, uint4* lo) {
    float f[8] = {v0.x, v0.y, v0.z, v0.w, v1.x, v1.y, v1.z, v1.w};
    uint32_t hw[4], lw[4];
    #pragma unroll
    for (int p = 0; p < 4; p++) {
        float a = f[2 * p], b = f[2 * p + 1];
        __nv_bfloat16 ha = __float2bfloat16_rn(a);
        __nv_bfloat16 hb = __float2bfloat16_rn(b);
        hw[p] = ((uint32_t)__bfloat16_as_ushort(hb) << 16) | __bfloat16_as_ushort(ha);
        lw[p] = pack_bf16x2(a - __bfloat162float(ha), b - __bfloat162float(hb));
    }
    *hi = *(uint4*)hw; *lo = *(uint4*)lw;
}

// ---------------- merged zero + edge-dtype detect (stream 2) ----------------
__global__ void zdetect_kernel(const int* __restrict__ ei32, int words, int n) {
    int i = blockIdx.x * blockDim.x + threadIdx.x;
    if (i < n) { g_deg[i] = 0; g_cursor[i] = 0; }
    if (blockIdx.x == 0) {
        __shared__ int flag;
        if (threadIdx.x == 0) flag = 0;
        __syncthreads();
        int acc = 0;
        for (int j = threadIdx.x * 2 + 1; j < words; j += 2 * 256 * 16) acc |= ei32[j];
        if (acc) atomicOr(&flag, 1);
        __syncthreads();
        if (threadIdx.x == 0) g_is64 = (flag == 0) ? 1 : 0;
    }
}

__device__ __forceinline__ int load_node(const void* ei, size_t idx) {
    if (g_is64) return (int)((const long long*)ei)[idx];
    return ((const int*)ei)[idx];
}

__global__ void hist_kernel(const void* __restrict__ ei, int E) {
    int e = blockIdx.x * blockDim.x + threadIdx.x;
    if (e < E) atomicAdd(&g_deg[load_node(ei, (size_t)E + e)], 1);
}

__global__ void dinv_kernel(int n) {
    int i = blockIdx.x * blockDim.x + threadIdx.x;
    if (i < n) g_dinv[i] = rsqrtf((float)(g_deg[i] + 1));
}

// ---------------- W1/W2 hi-lo split prep (main stream, no edge deps) ----------------
__global__ void wprep_kernel(const float* __restrict__ W1, const float* __restrict__ W2) {
    int i = blockIdx.x * blockDim.x + threadIdx.x;
    if (i < FIN * FH) {
        int k = i >> 7, c = i & 127;
        float w = W1[i];
        __nv_bfloat16 h = __float2bfloat16_rn(w);
        __nv_bfloat16 l = __float2bfloat16_rn(w - __bfloat162float(h));
        ((__nv_bfloat16*)g_W1h4)[k * LDA + c] = h;
        ((__nv_bfloat16*)g_W1l4)[k * LDA + c] = l;
    }
    if (i < FIN * 8) {
        int k = i >> 3, c = 128 + (i & 7);
        ((__nv_bfloat16*)g_W1h4)[k * LDA + c] = __float2bfloat16_rn(0.f);
        ((__nv_bfloat16*)g_W1l4)[k * LDA + c] = __float2bfloat16_rn(0.f);
    }
    if (i < FH * LDB2) {
        int k = i / LDB2, c = i % LDB2;
        float w = (c < FC) ? W2[k * FC + c] : 0.f;
        __nv_bfloat16 h = __float2bfloat16_rn(w);
        __nv_bfloat16 l = __float2bfloat16_rn(w - __bfloat162float(h));
        ((__nv_bfloat16*)g_W2h4)[k * LDB2 + c] = h;
        ((__nv_bfloat16*)g_W2l4)[k * LDB2 + c] = l;
    }
}

// ---------------- GEMM1: y = x @ W1 (UNscaled), 256 threads (R11 shape) ----------------
__global__ void __launch_bounds__(256) gemm1_wmma_kernel(const float* __restrict__ x, int n) {
    extern __shared__ char smem[];
    int tid = threadIdx.x;
    int r0 = blockIdx.x * G1_ROWS;

    // async-copy W1 hi/lo images into smem (overlaps A conversion below)
    {
        float4* dbh = (float4*)(smem + OFF_BH);
        float4* dbl = (float4*)(smem + OFF_BL);
        for (int i = tid; i < W1_IMG_F4; i += 256) {
            __pipeline_memcpy_async(dbh + i, g_W1h4 + i, 16);
            __pipeline_memcpy_async(dbl + i, g_W1l4 + i, 16);
        }
        __pipeline_commit();
    }

    // stage A: 128 rows, 2 threads/row (64 k each); split hi/lo (no scaling)
    {
        int r = tid >> 1, q = tid & 1;
        int gr = r0 + r; if (gr >= n) gr = n - 1;
        const float4* xr = (const float4*)(x + (size_t)gr * FIN) + q * 16;
        char* rowh = smem + OFF_AH + r * (LDA * 2) + q * 128;
        char* rowl = smem + OFF_AL + r * (LDA * 2) + q * 128;
        #pragma unroll
        for (int j = 0; j < 8; j++) {
            float4 v0 = xr[j * 2], v1 = xr[j * 2 + 1];
            uint4 hi, lo;
            split8(v0, v1, &hi, &lo);
            *(uint4*)(rowh + j * 16) = hi;
            *(uint4*)(rowl + j * 16) = lo;
        }
    }
    __pipeline_wait_prior(0);
    __syncthreads();

    int wid = tid >> 5;
    int wm = wid >> 1;            // 0..3
    int nh = wid & 1;             // 0..1

    wmma::fragment<wmma::accumulator, 16, 16, 16, float> fc[2][4];
    #pragma unroll
    for (int i = 0; i < 2; i++)
        #pragma unroll
        for (int nt = 0; nt < 4; nt++) wmma::fill_fragment(fc[i][nt], 0.f);

    const __nv_bfloat16* Ah = (const __nv_bfloat16*)(smem + OFF_AH) + wm * 32 * LDA;
    const __nv_bfloat16* Al = (const __nv_bfloat16*)(smem + OFF_AL) + wm * 32 * LDA;
    const __nv_bfloat16* Bh = (const __nv_bfloat16*)(smem + OFF_BH) + nh * 64;
    const __nv_bfloat16* Bl = (const __nv_bfloat16*)(smem + OFF_BL) + nh * 64;

    #pragma unroll
    for (int ks = 0; ks < 8; ks++) {
        wmma::fragment<wmma::matrix_a, 16, 16, 16, __nv_bfloat16, wmma::row_major> fah[2], fal[2];
        #pragma unroll
        for (int i = 0; i < 2; i++) {
            wmma::load_matrix_sync(fah[i], Ah + i * 16 * LDA + ks * 16, LDA);
            wmma::load_matrix_sync(fal[i], Al + i * 16 * LDA + ks * 16, LDA);
        }
        #pragma unroll
        for (int nt = 0; nt < 4; nt++) {
            wmma::fragment<wmma::matrix_b, 16, 16, 16, __nv_bfloat16, wmma::row_major> fbh, fbl;
            wmma::load_matrix_sync(fbh, Bh + ks * 16 * LDA + nt * 16, LDA);
            wmma::load_matrix_sync(fbl, Bl + ks * 16 * LDA + nt * 16, LDA);
            #pragma unroll
            for (int i = 0; i < 2; i++) {
                wmma::mma_sync(fc[i][nt], fah[i], fbh, fc[i][nt]);
                wmma::mma_sync(fc[i][nt], fal[i], fbh, fc[i][nt]);
                wmma::mma_sync(fc[i][nt], fah[i], fbl, fc[i][nt]);
            }
        }
    }

    float* yout = (float*)g_y4;
    #pragma unroll
    for (int i = 0; i < 2; i++)
        #pragma unroll
        for (int nt = 0; nt < 4; nt++)
            wmma::store_matrix_sync(yout + (size_t)(r0 + wm * 32 + i * 16) * FH + nh * 64 + nt * 16,
                                    fc[i][nt], FH, wmma::mem_row_major);
}

// ---------------- scans / scatter ----------------
__global__ void scan_block_kernel(int n) {
    __shared__ int s[512];
    int t = threadIdx.x;
    int i = blockIdx.x * 512 + t;
    int v = (i < n) ? g_deg[i] : 0;
    s[t] = v;
    __syncthreads();
    #pragma unroll
    for (int off = 1; off < 512; off <<= 1) {
        int u = (t >= off) ? s[t - off] : 0;
        __syncthreads();
        s[t] += u;
        __syncthreads();
    }
    if (i < n) g_rowstart[i] = s[t] - v;
    if (t == 511) g_bsums[blockIdx.x] = s[511];
}

__global__ void scan_top_kernel(int nb) {
    __shared__ int s[256];
    int t = threadIdx.x;
    int v = (t < nb) ? g_bsums[t] : 0;
    s[t] = v;
    __syncthreads();
    #pragma unroll
    for (int off = 1; off < 256; off <<= 1) {
        int u = (t >= off) ? s[t - off] : 0;
        __syncthreads();
        s[t] += u;
        __syncthreads();
    }
    if (t < nb) g_bsums[t] = s[t] - v;
}

__global__ void scan_add_kernel(int n) {
    int i = blockIdx.x * 512 + threadIdx.x;
    if (i < n) g_rowstart[i] += g_bsums[blockIdx.x];
}

__global__ void scatter_kernel(const void* __restrict__ ei, int E) {
    int e = blockIdx.x * blockDim.x + threadIdx.x;
    if (e < E) {
        int d = load_node(ei, (size_t)E + e);
        int s = load_node(ei, (size_t)e);
        int p = atomicAdd(&g_cursor[d], 1);
        g_adj[g_rowstart[d] + p] = s;
    }
}

// ---------------- agg1: h' = relu(dinv_d*(Σ dinv_s y_s + dinv_d y_d)+b1)*dinv_d ----------------
__global__ __launch_bounds__(256) void agg1_kernel(const float* __restrict__ b1, int n) {
    int gw = (blockIdx.x * blockDim.x + threadIdx.x) >> 5;
    int lane = threadIdx.x & 31;
    if (gw >= n) return;
    float di = g_dinv[gw];
    float4 self = g_y4[(size_t)gw * 32 + lane];
    float4 acc, acc2 = make_float4(0.f, 0.f, 0.f, 0.f);
    acc.x = self.x * di; acc.y = self.y * di; acc.z = self.z * di; acc.w = self.w * di;
    int s0 = g_rowstart[gw];
    int d  = g_deg[gw];
    int j = 0;
    for (; j + 1 < d; j += 2) {
        int sa = g_adj[s0 + j];
        int sb = g_adj[s0 + j + 1];
        float da = g_dinv[sa], db = g_dinv[sb];
        float4 va = g_y4[(size_t)sa * 32 + lane];
        float4 vb = g_y4[(size_t)sb * 32 + lane];
        acc.x = fmaf(va.x, da, acc.x);  acc.y = fmaf(va.y, da, acc.y);
        acc.z = fmaf(va.z, da, acc.z);  acc.w = fmaf(va.w, da, acc.w);
        acc2.x = fmaf(vb.x, db, acc2.x); acc2.y = fmaf(vb.y, db, acc2.y);
        acc2.z = fmaf(vb.z, db, acc2.z); acc2.w = fmaf(vb.w, db, acc2.w);
    }
    if (j < d) {
        int sa = g_adj[s0 + j];
        float da = g_dinv[sa];
        float4 va = g_y4[(size_t)sa * 32 + lane];
        acc.x = fmaf(va.x, da, acc.x); acc.y = fmaf(va.y, da, acc.y);
        acc.z = fmaf(va.z, da, acc.z); acc.w = fmaf(va.w, da, acc.w);
    }
    acc.x += acc2.x; acc.y += acc2.y; acc.z += acc2.z; acc.w += acc2.w;
    float4 bb = ((const float4*)b1)[lane];
    float4 o;
    o.x = fmaxf(fmaf(acc.x, di, bb.x), 0.f) * di;
    o.y = fmaxf(fmaf(acc.y, di, bb.y), 0.f) * di;
    o.z = fmaxf(fmaf(acc.z, di, bb.z), 0.f) * di;
    o.w = fmaxf(fmaf(acc.w, di, bb.w), 0.f) * di;
    __nv_bfloat16 hx = __float2bfloat16_rn(o.x), hy = __float2bfloat16_rn(o.y);
    __nv_bfloat16 hz = __float2bfloat16_rn(o.z), hw = __float2bfloat16_rn(o.w);
    uint2 hiw, low;
    hiw.x = ((uint32_t)__bfloat16_as_ushort(hy) << 16) | __bfloat16_as_ushort(hx);
    hiw.y = ((uint32_t)__bfloat16_as_ushort(hw) << 16) | __bfloat16_as_ushort(hz);
    low.x = pack_bf16x2(o.x - __bfloat162float(hx), o.y - __bfloat162float(hy));
    low.y = pack_bf16x2(o.z - __bfloat162float(hz), o.w - __bfloat162float(hw));
    ((uint2*)g_hh)[(size_t)gw * 32 + lane] = hiw;
    ((uint2*)g_hl)[(size_t)gw * 32 + lane] = low;
}

// ---------------- GEMM2: z = h' @ W2 (wmma bf16 3-term, N=48) ----------------
__global__ void __launch_bounds__(256) gemm2_wmma_kernel(int n) {
    extern __shared__ char smem[];
    int tid = threadIdx.x;
    int r0 = blockIdx.x * 128;

    {
        float4* dbh = (float4*)(smem + OFF2_BH);
        float4* dbl = (float4*)(smem + OFF2_BL);
        for (int i = tid; i < W2_IMG_F4; i += 256) {
            __pipeline_memcpy_async(dbh + i, g_W2h4 + i, 16);
            __pipeline_memcpy_async(dbl + i, g_W2l4 + i, 16);
        }
    }
    {
        int r = tid >> 1, q = tid & 1;
        int gr = r0 + r; if (gr >= n) gr = n - 1;
        const uint4* sh = g_hh + (size_t)gr * 16 + q * 8;
        const uint4* sl = g_hl + (size_t)gr * 16 + q * 8;
        char* rowh = smem + OFF2_AH + r * (LDA * 2) + q * 128;
        char* rowl = smem + OFF2_AL + r * (LDA * 2) + q * 128;
        #pragma unroll
        for (int j = 0; j < 8; j++) {
            __pipeline_memcpy_async(rowh + j * 16, sh + j, 16);
            __pipeline_memcpy_async(rowl + j * 16, sl + j, 16);
        }
    }
    __pipeline_commit();
    __pipeline_wait_prior(0);
    __syncthreads();

    int w = tid >> 5;
    wmma::fragment<wmma::accumulator, 16, 16, 16, float> fc[3];
    #pragma unroll
    for (int nt = 0; nt < 3; nt++) wmma::fill_fragment(fc[nt], 0.f);

    const __nv_bfloat16* Ah = (const __nv_bfloat16*)(smem + OFF2_AH) + w * 16 * LDA;
    const __nv_bfloat16* Al = (const __nv_bfloat16*)(smem + OFF2_AL) + w * 16 * LDA;
    const __nv_bfloat16* Bh = (const __nv_bfloat16*)(smem + OFF2_BH);
    const __nv_bfloat16* Bl = (const __nv_bfloat16*)(smem + OFF2_BL);

    #pragma unroll
    for (int ks = 0; ks < 8; ks++) {
        wmma::fragment<wmma::matrix_a, 16, 16, 16, __nv_bfloat16, wmma::row_major> fah, fal;
        wmma::load_matrix_sync(fah, Ah + ks * 16, LDA);
        wmma::load_matrix_sync(fal, Al + ks * 16, LDA);
        #pragma unroll
        for (int nt = 0; nt < 3; nt++) {
            wmma::fragment<wmma::matrix_b, 16, 16, 16, __nv_bfloat16, wmma::row_major> fbh, fbl;
            wmma::load_matrix_sync(fbh, Bh + ks * 16 * LDB2 + nt * 16, LDB2);
            wmma::load_matrix_sync(fbl, Bl + ks * 16 * LDB2 + nt * 16, LDB2);
            wmma::mma_sync(fc[nt], fah, fbh, fc[nt]);
            wmma::mma_sync(fc[nt], fal, fbh, fc[nt]);
            wmma::mma_sync(fc[nt], fah, fbl, fc[nt]);
        }
    }

    float* zout = (float*)g_z4;
    #pragma unroll
    for (int nt = 0; nt < 3; nt++)
        wmma::store_matrix_sync(zout + (size_t)(r0 + w * 16) * FCP + nt * 16, fc[nt], FCP,
                                wmma::mem_row_major);
}

// ---------------- agg2 + log_softmax (2 nodes per warp, z stride 48) ----------------
__global__ __launch_bounds__(256) void agg2_kernel(const float* __restrict__ b2,
                                                   float* __restrict__ out, int n) {
    int warp = (blockIdx.x * blockDim.x + threadIdx.x) >> 5;
    int lane = threadIdx.x & 31;
    int half = lane >> 4;
    int hl = lane & 15;
    int node = warp * 2 + half;
    bool valid = (node < n);
    bool act = valid && (hl < 10);
    float4 acc = make_float4(0.f, 0.f, 0.f, 0.f);
    if (act) acc = g_z4[(size_t)node * 12 + hl];
    int s0 = valid ? g_rowstart[node] : 0;
    int d  = valid ? g_deg[node] : 0;
    for (int j = 0; j < d; j++) {
        int s = g_adj[s0 + j];
        if (act) {
            float4 v = g_z4[(size_t)s * 12 + hl];
            acc.x += v.x; acc.y += v.y; acc.z += v.z; acc.w += v.w;
        }
    }
    float di = valid ? g_dinv[node] : 0.f;
    float4 l = make_float4(-INFINITY, -INFINITY, -INFINITY, -INFINITY);
    if (act) {
        float4 bb = *(const float4*)&b2[hl * 4];
        l.x = fmaf(acc.x, di, bb.x);
        l.y = fmaf(acc.y, di, bb.y);
        l.z = fmaf(acc.z, di, bb.z);
        l.w = fmaf(acc.w, di, bb.w);
    }
    float m = fmaxf(fmaxf(l.x, l.y), fmaxf(l.z, l.w));
    #pragma unroll
    for (int off = 8; off >= 1; off >>= 1)
        m = fmaxf(m, __shfl_xor_sync(0xffffffffu, m, off));
    float ssum = 0.f;
    if (act)
        ssum = expf(l.x - m) + expf(l.y - m) + expf(l.z - m) + expf(l.w - m);
    #pragma unroll
    for (int off = 8; off >= 1; off >>= 1)
        ssum += __shfl_xor_sync(0xffffffffu, ssum, off);
    float lse = m + logf(ssum);
    if (act) {
        float4 o;
        o.x = l.x - lse; o.y = l.y - lse; o.z = l.z - lse; o.w = l.w - lse;
        *(float4*)&out[(size_t)node * FC + hl * 4] = o;
    }
}

// ---------------- launch ----------------
extern "C" void kernel_launch(void* const* d_in, const int* in_sizes, int n_in,
                              void* d_out, int out_size) {
    const float* x  = (const float*)d_in[0];
    const void*  ei = d_in[1];
    const float* W1 = (const float*)d_in[2];
    const float* b1 = (const float*)d_in[3];
    const float* W2 = (const float*)d_in[4];
    const float* b2 = (const float*)d_in[5];
    float* out = (float*)d_out;

    int n = in_sizes[0] / FIN;   // 100000
    int E = in_sizes[1] / 2;     // 640000
    int NB = (n + 511) / 512;

    static cudaStream_t s2 = nullptr;
    static cudaEvent_t eFork = nullptr, eJoin = nullptr;
    static int init_done = 0;
    if (!init_done) {
        cudaFuncSetAttribute(gemm1_wmma_kernel,
                             cudaFuncAttributeMaxDynamicSharedMemorySize, SM1_TOTAL);
        cudaFuncSetAttribute(gemm2_wmma_kernel,
                             cudaFuncAttributeMaxDynamicSharedMemorySize, SM2_TOTAL);
        cudaStreamCreateWithFlags(&s2, cudaStreamNonBlocking);
        cudaEventCreateWithFlags(&eFork, cudaEventDisableTiming);
        cudaEventCreateWithFlags(&eJoin, cudaEventDisableTiming);
        init_done = 1;
    }

    // fork at t=0: ALL edge/CSR work on s2, independent of gemm1
    cudaEventRecord(eFork, 0);
    cudaStreamWaitEvent(s2, eFork, 0);

    zdetect_kernel<<<(n + 255) / 256, 256, 0, s2>>>((const int*)ei, 2 * E, n);
    hist_kernel<<<(E + 255) / 256, 256, 0, s2>>>(ei, E);
    dinv_kernel<<<(n + 255) / 256, 256, 0, s2>>>(n);
    scan_block_kernel<<<NB, 512, 0, s2>>>(n);
    scan_top_kernel<<<1, 256, 0, s2>>>(NB);
    scan_add_kernel<<<NB, 512, 0, s2>>>(n);
    scatter_kernel<<<(E + 255) / 256, 256, 0, s2>>>(ei, E);
    cudaEventRecord(eJoin, s2);

    // main stream: weight prep + gemm1 (no edge/dinv dependence)
    wprep_kernel<<<(FIN * FH + 255) / 256, 256>>>(W1, W2);
    gemm1_wmma_kernel<<<(n + G1_ROWS - 1) / G1_ROWS, 256, SM1_TOTAL>>>(x, n);

    // join before aggregation (needs CSR + dinv + y)
    cudaStreamWaitEvent(0, eJoin, 0);

    agg1_kernel<<<(n * 32 + 255) / 256, 256>>>(b1, n);
    gemm2_wmma_kernel<<<(n + 127) / 128, 256, SM2_TOTAL>>>(n);
    int warps2 = (n + 1) / 2;
    agg2_kernel<<<(warps2 * 32 + 255) / 256, 256>>>(b2, out, n);
}